// round 16
// baseline (speedup 1.0000x reference)
#include <cuda_runtime.h>

// x:(T,B,NI) W1:(NH,NI) b1:(NH) W2:(NO,NH) b2:(NO)
// out = concat(spk1[T,B,NH], mem1[T,B,NH], spk2[T,B,NO], mem2[T,B,NO])
#define T_STEPS 100
#define BATCH   65536
#define NI      2
#define NH      10
#define NO      4
#define BETA    0.5f
#define THRV    1.0f

#define BLOCK_THREADS 128
#define GROUP   10                 // steps per x-batch
#define NGRP    (T_STEPS / GROUP)  // 10
#define XCHUNK_F4 64               // f4 per step per block (128 batch * 2 floats)

// per-block smem staging regions (in floats) — R8 layout
#define SPK1_OFF 0
#define MEM1_OFF (BLOCK_THREADS * NH)                           // 1280
#define SPK2_OFF (2 * BLOCK_THREADS * NH)                       // 2560
#define MEM2_OFF (2 * BLOCK_THREADS * NH + BLOCK_THREADS * NO)  // 3072
#define BUF_FLOATS (BLOCK_THREADS * (2 * NH + 2 * NO))          // 3584

__global__ __launch_bounds__(BLOCK_THREADS) void snn_kernel(
    const float* __restrict__ x,
    const float* __restrict__ W1,
    const float* __restrict__ b1,
    const float* __restrict__ W2,
    const float* __restrict__ b2,
    float* __restrict__ out)
{
    __shared__ float  sbuf[2][BUF_FLOATS];            // 28.7 KB
    __shared__ float4 xs[2][GROUP * XCHUNK_F4];       // 20 KB, double buffered

    const int tid = threadIdx.x;
    const int b0  = blockIdx.x * BLOCK_THREADS;

    // ---- weights into registers ----
    float w1a[NH], w1b[NH], bb1[NH];
#pragma unroll
    for (int h = 0; h < NH; h++) {
        w1a[h] = __ldg(W1 + h * NI + 0);
        w1b[h] = __ldg(W1 + h * NI + 1);
        bb1[h] = __ldg(b1 + h);
    }
    float w2[NO][NH], bb2[NO];
#pragma unroll
    for (int o = 0; o < NO; o++) {
        bb2[o] = __ldg(b2 + o);
#pragma unroll
        for (int h = 0; h < NH; h++) w2[o][h] = __ldg(W2 + o * NH + h);
    }

    // ---- state ----
    float mem1[NH];
    float mem2[NO];
#pragma unroll
    for (int h = 0; h < NH; h++) mem1[h] = 0.0f;
#pragma unroll
    for (int o = 0; o < NO; o++) mem2[o] = 0.0f;

    // ---- output bases ----
    float* const oSpk1 = out;
    float* const oMem1 = out + (size_t)T_STEPS * BATCH * NH;
    float* const oSpk2 = out + (size_t)2 * T_STEPS * BATCH * NH;
    float* const oMem2 = oSpk2 + (size_t)T_STEPS * BATCH * NO;

    // ---- cooperative batched x load: one 10 KB burst per group ----
    // x region for step t of this block: 1024B contiguous at (t*BATCH + b0)*NI floats
    // group = 10 chunks of 64 f4 = 640 f4 = 5 iterations of 128 threads
    {
        // preload group 0 into xs[0]
#pragma unroll
        for (int k = 0; k < 5; k++) {
            const int i = k * BLOCK_THREADS + tid;
            const int s = i >> 6, j = i & 63;
            const float4* src = reinterpret_cast<const float4*>(
                x + ((size_t)s * BATCH + b0) * NI);
            xs[0][s * XCHUNK_F4 + j] = __ldg(&src[j]);
        }
    }
    __syncthreads();

    for (int g = 0; g < NGRP; g++) {
        const int p = g & 1;
        const int t0 = g * GROUP;

        // prefetch next group's x (clamped; last-group prefetch is redundant
        // but harmless — it targets the opposite parity)
        {
            const int gn = (g + 1 < NGRP) ? (g + 1) : g;
            const int tn0 = gn * GROUP;
#pragma unroll
            for (int k = 0; k < 5; k++) {
                const int i = k * BLOCK_THREADS + tid;
                const int s = i >> 6, j = i & 63;
                const float4* src = reinterpret_cast<const float4*>(
                    x + ((size_t)(tn0 + s) * BATCH + b0) * NI);
                xs[1 - p][s * XCHUNK_F4 + j] = __ldg(&src[j]);
            }
        }

#pragma unroll
        for (int s = 0; s < GROUP; s++) {
            const int t = t0 + s;
            const float2 xv =
                reinterpret_cast<const float2*>(&xs[p][s * XCHUNK_F4])[tid];
            const float x0 = xv.x, x1 = xv.y;
            float* const buf = sbuf[t & 1];

            // ---- layer 1 LIF -> smem ----
            float spk1[NH];
#pragma unroll
            for (int h = 0; h < NH; h++) {
                float syn   = fmaf(x0, w1a[h], fmaf(x1, w1b[h], bb1[h]));
                float reset = (mem1[h] > THRV) ? THRV : 0.0f;
                float m     = fmaf(BETA, mem1[h], syn) - reset;
                mem1[h]     = m;
                spk1[h]     = (m > THRV) ? 1.0f : 0.0f;
            }
            {
                float2* ps = reinterpret_cast<float2*>(buf + SPK1_OFF + tid * NH);
                float2* pm = reinterpret_cast<float2*>(buf + MEM1_OFF + tid * NH);
#pragma unroll
                for (int i = 0; i < NH / 2; i++) {
                    ps[i] = make_float2(spk1[2 * i], spk1[2 * i + 1]);
                    pm[i] = make_float2(mem1[2 * i], mem1[2 * i + 1]);
                }
            }

            // ---- layer 2 LIF -> smem ----
            float spk2[NO];
#pragma unroll
            for (int o = 0; o < NO; o++) {
                float syn = bb2[o];
#pragma unroll
                for (int h = 0; h < NH; h++) syn = fmaf(spk1[h], w2[o][h], syn);
                float reset = (mem2[o] > THRV) ? THRV : 0.0f;
                float m     = fmaf(BETA, mem2[o], syn) - reset;
                mem2[o]     = m;
                spk2[o]     = (m > THRV) ? 1.0f : 0.0f;
            }
            {
                float4* ps = reinterpret_cast<float4*>(buf + SPK2_OFF + tid * NO);
                float4* pm = reinterpret_cast<float4*>(buf + MEM2_OFF + tid * NO);
                ps[0] = make_float4(spk2[0], spk2[1], spk2[2], spk2[3]);
                pm[0] = make_float4(mem2[0], mem2[1], mem2[2], mem2[3]);
            }

            __syncthreads();

            // ---- cooperative fully-coalesced streaming stores (R8) ----
            {
                const float4* s4 = reinterpret_cast<const float4*>(buf);
                float4* g4 = reinterpret_cast<float4*>(
                    oSpk1 + (size_t)t * BATCH * NH + (size_t)b0 * NH);
#pragma unroll
                for (int i = tid; i < (BLOCK_THREADS * NH) / 4; i += BLOCK_THREADS)
                    __stcs(&g4[i], s4[SPK1_OFF / 4 + i]);
                g4 = reinterpret_cast<float4*>(
                    oMem1 + (size_t)t * BATCH * NH + (size_t)b0 * NH);
#pragma unroll
                for (int i = tid; i < (BLOCK_THREADS * NH) / 4; i += BLOCK_THREADS)
                    __stcs(&g4[i], s4[MEM1_OFF / 4 + i]);
                g4 = reinterpret_cast<float4*>(
                    oSpk2 + (size_t)t * BATCH * NO + (size_t)b0 * NO);
                __stcs(&g4[tid], s4[SPK2_OFF / 4 + tid]);
                g4 = reinterpret_cast<float4*>(
                    oMem2 + (size_t)t * BATCH * NO + (size_t)b0 * NO);
                __stcs(&g4[tid], s4[MEM2_OFF / 4 + tid]);
            }
        }
    }
}

extern "C" void kernel_launch(void* const* d_in, const int* in_sizes, int n_in,
                              void* d_out, int out_size) {
    const float* x  = (const float*)d_in[0];
    const float* W1 = (const float*)d_in[1];
    const float* b1 = (const float*)d_in[2];
    const float* W2 = (const float*)d_in[3];
    const float* b2 = (const float*)d_in[4];
    float* out = (float*)d_out;

    snn_kernel<<<BATCH / BLOCK_THREADS, BLOCK_THREADS>>>(x, W1, b1, W2, b2, out);
}

// round 17
// speedup vs baseline: 1.2257x; 1.2257x over previous
#include <cuda_runtime.h>

// x:(T,B,NI) W1:(NH,NI) b1:(NH) W2:(NO,NH) b2:(NO)
// out = concat(spk1[T,B,NH], mem1[T,B,NH], spk2[T,B,NO], mem2[T,B,NO])
//
// FINAL KERNEL (R8 structure; reproduced 127.0/127.1/127.7 us).
// HBM-write-bound: 786 MB mandatory traffic at the measured ~5.8 TB/s
// mixed-stream ceiling -> ~125 us floor. One thread per batch element carries
// the LIF recurrence in registers; outputs staged per-step in double-buffered
// smem (b-major = global layout); one __syncthreads per step; block-wide
// fully-coalesced STG.128 streaming bursts. 124 regs / 4 blocks/SM — proven
// to be the occupancy/burst-density optimum (R3-R16 variations all regressed).
#define T_STEPS 100
#define BATCH   65536
#define NI      2
#define NH      10
#define NO      4
#define BETA    0.5f
#define THRV    1.0f

#define BLOCK_THREADS 128

// per-block smem staging regions (in floats)
#define SPK1_OFF 0
#define MEM1_OFF (BLOCK_THREADS * NH)                           // 1280
#define SPK2_OFF (2 * BLOCK_THREADS * NH)                       // 2560
#define MEM2_OFF (2 * BLOCK_THREADS * NH + BLOCK_THREADS * NO)  // 3072
#define BUF_FLOATS (BLOCK_THREADS * (2 * NH + 2 * NO))          // 3584

__global__ __launch_bounds__(BLOCK_THREADS) void snn_kernel(
    const float* __restrict__ x,
    const float* __restrict__ W1,
    const float* __restrict__ b1,
    const float* __restrict__ W2,
    const float* __restrict__ b2,
    float* __restrict__ out)
{
    __shared__ float sbuf[2][BUF_FLOATS];

    const int tid = threadIdx.x;
    const int b   = blockIdx.x * BLOCK_THREADS + tid;
    const int b0  = blockIdx.x * BLOCK_THREADS;

    // ---- weights into registers ----
    float w1a[NH], w1b[NH], bb1[NH];
#pragma unroll
    for (int h = 0; h < NH; h++) {
        w1a[h] = __ldg(W1 + h * NI + 0);
        w1b[h] = __ldg(W1 + h * NI + 1);
        bb1[h] = __ldg(b1 + h);
    }
    float w2[NO][NH], bb2[NO];
#pragma unroll
    for (int o = 0; o < NO; o++) {
        bb2[o] = __ldg(b2 + o);
#pragma unroll
        for (int h = 0; h < NH; h++) w2[o][h] = __ldg(W2 + o * NH + h);
    }

    // ---- state ----
    float mem1[NH];
    float mem2[NO];
#pragma unroll
    for (int h = 0; h < NH; h++) mem1[h] = 0.0f;
#pragma unroll
    for (int o = 0; o < NO; o++) mem2[o] = 0.0f;

    // ---- output bases ----
    float* const oSpk1 = out;
    float* const oMem1 = out + (size_t)T_STEPS * BATCH * NH;
    float* const oSpk2 = out + (size_t)2 * T_STEPS * BATCH * NH;
    float* const oMem2 = oSpk2 + (size_t)T_STEPS * BATCH * NO;

    const float2* __restrict__ xp = reinterpret_cast<const float2*>(x);

    // 2-deep prefetch pipeline for x
    float2 xv  = __ldg(&xp[(size_t)0 * BATCH + b]);
    float2 xv1 = __ldg(&xp[(size_t)1 * BATCH + b]);

    for (int t = 0; t < T_STEPS; t++) {
        float2 xnext;
        if (t + 2 < T_STEPS) xnext = __ldg(&xp[(size_t)(t + 2) * BATCH + b]);
        else                 xnext = make_float2(0.0f, 0.0f);

        const float x0 = xv.x, x1 = xv.y;
        float* const buf = sbuf[t & 1];

        // ---- layer 1 LIF -> smem ----
        float spk1[NH];
#pragma unroll
        for (int h = 0; h < NH; h++) {
            float syn   = fmaf(x0, w1a[h], fmaf(x1, w1b[h], bb1[h]));
            float reset = (mem1[h] > THRV) ? THRV : 0.0f;
            float m     = fmaf(BETA, mem1[h], syn) - reset;
            mem1[h]     = m;
            spk1[h]     = (m > THRV) ? 1.0f : 0.0f;
        }
        {
            float2* ps = reinterpret_cast<float2*>(buf + SPK1_OFF + tid * NH);
            float2* pm = reinterpret_cast<float2*>(buf + MEM1_OFF + tid * NH);
#pragma unroll
            for (int i = 0; i < NH / 2; i++) {
                ps[i] = make_float2(spk1[2 * i], spk1[2 * i + 1]);
                pm[i] = make_float2(mem1[2 * i], mem1[2 * i + 1]);
            }
        }

        // ---- layer 2 LIF -> smem ----
        float spk2[NO];
#pragma unroll
        for (int o = 0; o < NO; o++) {
            float syn = bb2[o];
#pragma unroll
            for (int h = 0; h < NH; h++) syn = fmaf(spk1[h], w2[o][h], syn);
            float reset = (mem2[o] > THRV) ? THRV : 0.0f;
            float m     = fmaf(BETA, mem2[o], syn) - reset;
            mem2[o]     = m;
            spk2[o]     = (m > THRV) ? 1.0f : 0.0f;
        }
        {
            float4* ps = reinterpret_cast<float4*>(buf + SPK2_OFF + tid * NO);
            float4* pm = reinterpret_cast<float4*>(buf + MEM2_OFF + tid * NO);
            ps[0] = make_float4(spk2[0], spk2[1], spk2[2], spk2[3]);
            pm[0] = make_float4(mem2[0], mem2[1], mem2[2], mem2[3]);
        }

        __syncthreads();

        // ---- cooperative fully-coalesced streaming stores ----
        {
            const float4* s4 = reinterpret_cast<const float4*>(buf);
            // spk1: 1280 floats = 320 float4
            float4* g = reinterpret_cast<float4*>(oSpk1 + (size_t)t * BATCH * NH + (size_t)b0 * NH);
#pragma unroll
            for (int i = tid; i < (BLOCK_THREADS * NH) / 4; i += BLOCK_THREADS)
                __stcs(&g[i], s4[SPK1_OFF / 4 + i]);
            // mem1
            g = reinterpret_cast<float4*>(oMem1 + (size_t)t * BATCH * NH + (size_t)b0 * NH);
#pragma unroll
            for (int i = tid; i < (BLOCK_THREADS * NH) / 4; i += BLOCK_THREADS)
                __stcs(&g[i], s4[MEM1_OFF / 4 + i]);
            // spk2: 512 floats = 128 float4 -> one per thread
            g = reinterpret_cast<float4*>(oSpk2 + (size_t)t * BATCH * NO + (size_t)b0 * NO);
            __stcs(&g[tid], s4[SPK2_OFF / 4 + tid]);
            // mem2
            g = reinterpret_cast<float4*>(oMem2 + (size_t)t * BATCH * NO + (size_t)b0 * NO);
            __stcs(&g[tid], s4[MEM2_OFF / 4 + tid]);
        }

        xv  = xv1;
        xv1 = xnext;
    }
}

extern "C" void kernel_launch(void* const* d_in, const int* in_sizes, int n_in,
                              void* d_out, int out_size) {
    const float* x  = (const float*)d_in[0];
    const float* W1 = (const float*)d_in[1];
    const float* b1 = (const float*)d_in[2];
    const float* W2 = (const float*)d_in[3];
    const float* b2 = (const float*)d_in[4];
    float* out = (float*)d_out;

    snn_kernel<<<BATCH / BLOCK_THREADS, BLOCK_THREADS>>>(x, W1, b1, W2, b2, out);
}